// round 3
// baseline (speedup 1.0000x reference)
#include <cuda_runtime.h>
#include <cstdint>

#define NN 20000
#define BB 64
#define EE 1280000

// Scratch (allocation-free -> __device__ globals)
__device__ float g_xT[NN * BB];        // x transposed to [N, B]
__device__ int   g_count[NN];          // per-dst degree histogram
__device__ int   g_offset[NN + 1];     // exclusive prefix (bin starts)
__device__ int   g_cursor[NN];         // scatter cursors
__device__ uint2 g_bin[EE];            // per-edge record: (src, coeff bits), binned by dst

// ---------------------------------------------------------------------------
// K0: transpose x [B,N] -> xT [N,B]; zero the dst histogram.
// ---------------------------------------------------------------------------
__global__ void k_transpose(const float* __restrict__ x) {
    __shared__ float tile[64][65];
    const int n0 = blockIdx.x * 64;

    for (int i = blockIdx.x * blockDim.x + threadIdx.x; i < NN;
         i += gridDim.x * blockDim.x)
        g_count[i] = 0;

    #pragma unroll
    for (int i = threadIdx.x; i < 64 * 64; i += 256) {
        int bb = i >> 6;
        int nl = i & 63;
        int n = n0 + nl;
        tile[nl][bb] = (n < NN) ? x[bb * NN + n] : 0.0f;
    }
    __syncthreads();

    #pragma unroll
    for (int i = threadIdx.x; i < 64 * 64; i += 256) {
        int nl = i >> 6;
        int bb = i & 63;
        int n = n0 + nl;
        if (n < NN) g_xT[n * 64 + bb] = tile[nl][bb];
    }
}

// ---------------------------------------------------------------------------
// K1: dst histogram. Atomics spread over 20000 counters -> fast.
// ---------------------------------------------------------------------------
__global__ void k_hist(const int* __restrict__ dst) {
    int e = blockIdx.x * blockDim.x + threadIdx.x;
    if (e < EE) atomicAdd(&g_count[__ldg(&dst[e])], 1);
}

// ---------------------------------------------------------------------------
// K2: single-block exclusive scan over 20000 counters -> g_offset, g_cursor.
// 1024 threads, ~20 elements each; Hillis-Steele over the 1024 partials.
// ---------------------------------------------------------------------------
__global__ void k_scan() {
    __shared__ int partials[1024];
    const int CH = (NN + 1023) / 1024;  // 20
    int t = threadIdx.x;
    int base = t * CH;

    int local[CH];
    int s = 0;
    #pragma unroll
    for (int i = 0; i < CH; i++) {
        int idx = base + i;
        int c = (idx < NN) ? g_count[idx] : 0;
        local[i] = s;   // exclusive within chunk
        s += c;
    }
    partials[t] = s;
    __syncthreads();

    #pragma unroll
    for (int d = 1; d < 1024; d <<= 1) {
        int add = (t >= d) ? partials[t - d] : 0;
        __syncthreads();
        partials[t] += add;
        __syncthreads();
    }
    int pre = partials[t] - s;  // exclusive prefix of this chunk

    #pragma unroll
    for (int i = 0; i < CH; i++) {
        int idx = base + i;
        if (idx < NN) {
            int off = pre + local[i];
            g_offset[idx] = off;
            g_cursor[idx] = off;
        }
    }
    if (t == 1023) g_offset[NN] = pre + s;  // == EE
}

// ---------------------------------------------------------------------------
// K3: scatter edges into dst-sorted bins as packed (src, coeff) records.
// ---------------------------------------------------------------------------
__global__ void k_scatter(const float* __restrict__ adj,
                          const float* __restrict__ w,
                          const int* __restrict__ src,
                          const int* __restrict__ dst) {
    int e = blockIdx.x * blockDim.x + threadIdx.x;
    if (e >= EE) return;
    int d = __ldg(&dst[e]);
    int pos = atomicAdd(&g_cursor[d], 1);
    float c = __ldg(&adj[e]) * __ldg(&w[e]);
    g_bin[pos] = make_uint2((unsigned)__ldg(&src[e]), __float_as_uint(c));
}

// ---------------------------------------------------------------------------
// K4: warp-per-node register accumulation + fused epilogue.
// Lane l owns features [2l, 2l+1] (float2). Unroll-by-4 for MLP.
// out[b*N+n] = relu(acc * x[0,n]*self_w[n] + bias[n]).
// ---------------------------------------------------------------------------
__global__ void k_accum(const float* __restrict__ x,
                        const float* __restrict__ self_w,
                        const float* __restrict__ bias,
                        float* __restrict__ out) {
    int gwarp = (blockIdx.x * blockDim.x + threadIdx.x) >> 5;
    int lane = threadIdx.x & 31;
    if (gwarp >= NN) return;
    const int n = gwarp;

    int k = __ldg(&g_offset[n]);
    const int end = __ldg(&g_offset[n + 1]);

    float ax = 0.0f, ay = 0.0f;

    for (; k + 4 <= end; k += 4) {
        uint2 r0 = g_bin[k + 0];
        uint2 r1 = g_bin[k + 1];
        uint2 r2 = g_bin[k + 2];
        uint2 r3 = g_bin[k + 3];
        float2 v0 = reinterpret_cast<const float2*>(g_xT + (size_t)r0.x * 64)[lane];
        float2 v1 = reinterpret_cast<const float2*>(g_xT + (size_t)r1.x * 64)[lane];
        float2 v2 = reinterpret_cast<const float2*>(g_xT + (size_t)r2.x * 64)[lane];
        float2 v3 = reinterpret_cast<const float2*>(g_xT + (size_t)r3.x * 64)[lane];
        float c0 = __uint_as_float(r0.y);
        float c1 = __uint_as_float(r1.y);
        float c2 = __uint_as_float(r2.y);
        float c3 = __uint_as_float(r3.y);
        ax = fmaf(c0, v0.x, ax); ay = fmaf(c0, v0.y, ay);
        ax = fmaf(c1, v1.x, ax); ay = fmaf(c1, v1.y, ay);
        ax = fmaf(c2, v2.x, ax); ay = fmaf(c2, v2.y, ay);
        ax = fmaf(c3, v3.x, ax); ay = fmaf(c3, v3.y, ay);
    }
    for (; k < end; k++) {
        uint2 r = g_bin[k];
        float2 v = reinterpret_cast<const float2*>(g_xT + (size_t)r.x * 64)[lane];
        float c = __uint_as_float(r.y);
        ax = fmaf(c, v.x, ax); ay = fmaf(c, v.y, ay);
    }

    float sl = __ldg(&x[n]) * __ldg(&self_w[n]);  // x row 0
    float bs = __ldg(&bias[n]);
    float o0 = fmaxf(fmaf(ax, sl, bs), 0.0f);
    float o1 = fmaxf(fmaf(ay, sl, bs), 0.0f);
    out[(size_t)(2 * lane) * NN + n] = o0;
    out[(size_t)(2 * lane + 1) * NN + n] = o1;
}

// ---------------------------------------------------------------------------
// Launch. Inputs: x, adj_values, w, self_w, b, src, dst.
// ---------------------------------------------------------------------------
extern "C" void kernel_launch(void* const* d_in, const int* in_sizes, int n_in,
                              void* d_out, int out_size) {
    const float* x      = (const float*)d_in[0];
    const float* adj    = (const float*)d_in[1];
    const float* w      = (const float*)d_in[2];
    const float* self_w = (const float*)d_in[3];
    const float* bias   = (const float*)d_in[4];
    const int*   src    = (const int*)d_in[5];
    const int*   dst    = (const int*)d_in[6];
    float* out = (float*)d_out;

    const int n_tiles = (NN + 63) / 64;          // 313
    const int e_blocks = (EE + 255) / 256;       // 5000

    k_transpose<<<n_tiles, 256>>>(x);
    k_hist<<<e_blocks, 256>>>(dst);
    k_scan<<<1, 1024>>>();
    k_scatter<<<e_blocks, 256>>>(adj, w, src, dst);

    const int acc_blocks = (NN * 32 + 255) / 256;  // 2500
    k_accum<<<acc_blocks, 256>>>(x, self_w, bias, out);
}